// round 7
// baseline (speedup 1.0000x reference)
#include <cuda_runtime.h>
#include <cuda_bf16.h>
#include <cstdint>

// Problem constants (fixed shapes)
#define DD   256   // feature dim
#define KK   256   // num centers
#define OUTD 128   // output dim

// ---------------- constant precompute scratch (device globals) ----------------
__device__ __align__(16) float          g_s[DD];     // relu(sigma)
__device__ __align__(16) float          g_SV[OUTD];  // sum_k V[k,o]
__device__ __align__(16) float          g_Bp[OUTD];  // relu(W0)+sum relu(Wk) - sum c2*V
// Packed B fragments (bf16): uint4 index = (k16*8 + j)*32 + lane, j covers n-tiles {2j,2j+1}
__device__ __align__(16) __nv_bfloat16  g_Bpk[16 * 8 * 32 * 4 * 2];   // 64KB

// ---------------- packed-B writer ----------------
__device__ __forceinline__ void write_Bpk(int o, int d, float val) {
    int nt = o >> 3, q = o & 7;
    int k16 = d >> 4, r = d & 15;
    int i = r >> 3, l = (r & 7) >> 1, h = r & 1;
    int lane = q * 4 + l;
    int u32idx = ((k16 * 8 + (nt >> 1)) * 32 + lane) * 4 + (nt & 1) * 2 + i;
    g_Bpk[u32idx * 2 + h] = __float2bfloat16(val);
}

// ---------------- fused prep: SV, Bp, packed M2 — 2 output cols per block ------
__global__ void prep_kernel(const float* __restrict__ sigma,
                            const float* __restrict__ center,
                            const float* __restrict__ width,
                            const float* __restrict__ wout) {
    const int o0 = blockIdx.x * 2;
    const int o1 = o0 + 1;
    const int t = threadIdx.x;       // k index for reductions, d index for M2/CV
    __shared__ float V0[KK], V1[KK];
    __shared__ float red[6][8];

    const float s = fmaxf(sigma[t], 0.0f);
    if (blockIdx.x == 0) g_s[t] = s;

    float wk = fmaxf(width[t], 0.0f);
    float w0 = fmaxf(wout[(1 + t) * OUTD + o0], 0.0f);
    float w1 = fmaxf(wout[(1 + t) * OUTD + o1], 0.0f);
    float v0 = wk * w0, v1 = wk * w1;
    V0[t] = v0; V1[t] = v1;

    float r0 = v0, r1 = w0, r3 = v1, r4 = w1;
    #pragma unroll
    for (int off = 16; off; off >>= 1) {
        r0 += __shfl_xor_sync(0xffffffffu, r0, off);
        r1 += __shfl_xor_sync(0xffffffffu, r1, off);
        r3 += __shfl_xor_sync(0xffffffffu, r3, off);
        r4 += __shfl_xor_sync(0xffffffffu, r4, off);
    }
    const int warp = t >> 5, lane = t & 31;
    if (lane == 0) {
        red[0][warp] = r0; red[1][warp] = r1;
        red[3][warp] = r3; red[4][warp] = r4;
    }
    __syncthreads();   // V0/V1 ready

    // M2[d=t][o] = 2*sum_k c[k][t]*V[k][o];  CV partial: s_t * sum_k c[k][t]^2 * V[k][o]
    float m0 = 0, m1 = 0, q0 = 0, q1 = 0;
    #pragma unroll 4
    for (int k = 0; k < KK; k++) {
        float c = center[k * DD + t];
        float cs = c * c;
        m0 = fmaf(c, V0[k], m0);
        m1 = fmaf(c, V1[k], m1);
        q0 = fmaf(cs, V0[k], q0);
        q1 = fmaf(cs, V1[k], q1);
    }
    write_Bpk(o0, t, 2.0f * m0);
    write_Bpk(o1, t, 2.0f * m1);

    q0 *= s; q1 *= s;
    #pragma unroll
    for (int off = 16; off; off >>= 1) {
        q0 += __shfl_xor_sync(0xffffffffu, q0, off);
        q1 += __shfl_xor_sync(0xffffffffu, q1, off);
    }
    if (lane == 0) { red[2][warp] = q0; red[5][warp] = q1; }
    __syncthreads();

    if (t < 2) {
        const int o = (t == 0) ? o0 : o1;
        const float* a = red[3 * t];
        const float* b = red[3 * t + 1];
        const float* c = red[3 * t + 2];
        float sv = 0, sw = 0, cv = 0;
        #pragma unroll
        for (int w = 0; w < 8; w++) { sv += a[w]; sw += b[w]; cv += c[w]; }
        g_SV[o] = sv;
        g_Bp[o] = fmaxf(wout[o], 0.0f) + sw - cv;
    }
}

// ---------------- helpers ----------------
__device__ __forceinline__ uint32_t pack_bf16x2(float lo, float hi) {
    uint32_t r;
    asm("cvt.rn.bf16x2.f32 %0, %1, %2;" : "=r"(r) : "f"(hi), "f"(lo));
    return r;
}

__device__ __forceinline__ void mma16816(float* c, uint32_t a0, uint32_t a1,
                                         uint32_t a2, uint32_t a3,
                                         uint32_t b0, uint32_t b1) {
    asm volatile(
        "mma.sync.aligned.m16n8k16.row.col.f32.bf16.bf16.f32 "
        "{%0,%1,%2,%3}, {%4,%5,%6,%7}, {%8,%9}, {%0,%1,%2,%3};"
        : "+f"(c[0]), "+f"(c[1]), "+f"(c[2]), "+f"(c[3])
        : "r"(a0), "r"(a1), "r"(a2), "r"(a3), "r"(b0), "r"(b1));
}

__device__ __forceinline__ void ldsm_x4(uint32_t& r0, uint32_t& r1,
                                        uint32_t& r2, uint32_t& r3, uint32_t addr) {
    asm volatile("ldmatrix.sync.aligned.m8n8.x4.shared.b16 {%0,%1,%2,%3}, [%4];"
        : "=r"(r0), "=r"(r1), "=r"(r2), "=r"(r3) : "r"(addr));
}

// ---------------- main kernel: out = Bp - x2*SV + xs @ M2 ----------------
// 256 threads = 8 warps, warp grid 4(m) x 2(n), warp tile 32x64.
// Block tile 128 rows x 128 cols. Double-buffered A, ONE sync per chunk.
// Per-warp q-rotation de-phase-locks post-barrier load/MMA bursts.
__global__ void __launch_bounds__(256, 2)
rbf_main_kernel(const float* __restrict__ x, float* __restrict__ out) {
    __shared__ __align__(16) char smA[2][16384];   // bf16 A tiles (128x64 each)
    __shared__ float x2_sh[128];

    const int tid  = threadIdx.x;
    const int warp = tid >> 5;
    const int lane = tid & 31;
    const int warp_m = warp >> 1;     // 0..3
    const int warp_n = warp & 1;      // 0..1
    const int q8    = lane >> 2;      // 0..7
    const int qlane = lane & 3;       // 0..3
    const int rot   = ((warp & 3) + 2 * (warp >> 2)) & 3;   // SMSP-diverse rotation

    const int row0 = blockIdx.x * 128;
    const int srow = tid >> 4;        // 0..15
    const int scol = tid & 15;        // 0..15

    const uint32_t abase = (uint32_t)__cvta_generic_to_shared(smA);
    const uint4* Bb = reinterpret_cast<const uint4*>(g_Bpk) + warp_n * 128 + lane;
    const int row_l = warp_m * 32 + (lane & 15);
    const uint32_t lds_swz  = (uint32_t)((row_l & 7) << 4);
    const uint32_t lds_koff = (uint32_t)((lane >> 4) << 4);
    const uint32_t sts_base = abase
        + (uint32_t)(srow * 128 + ((scol * 8) ^ ((srow & 7) << 4)));

    float acc[2][8][4];
    #pragma unroll
    for (int mt = 0; mt < 2; mt++)
        #pragma unroll
        for (int nt = 0; nt < 8; nt++)
            #pragma unroll
            for (int i = 0; i < 4; i++) acc[mt][nt][i] = 0.0f;

    float x2p[8] = {0, 0, 0, 0, 0, 0, 0, 0};

    // prologue: load chunk 0 (rows p*16+srow, fully coalesced LDG.128)
    const float* xbase = x + (size_t)(row0 + srow) * DD + scol * 4;
    float4 v[8];
    #pragma unroll
    for (int p = 0; p < 8; p++)
        v[p] = __ldcs(reinterpret_cast<const float4*>(xbase + (size_t)p * 16 * DD));

    #pragma unroll
    for (int c = 0; c < 4; c++) {
        const float4 sv4 = *reinterpret_cast<const float4*>(g_s + c * 64 + scol * 4);
        const uint32_t ab = sts_base + (uint32_t)((c & 1) * 16384);

        // convert + STS + x2 accumulate (consumes v[])
        #pragma unroll
        for (int p = 0; p < 8; p++) {
            const float4 w = v[p];
            float a = w.x * sv4.x, b = w.y * sv4.y, cc2 = w.z * sv4.z, d = w.w * sv4.w;
            x2p[p] += a * w.x + b * w.y + cc2 * w.z + d * w.w;
            uint2 packed = make_uint2(pack_bf16x2(a, b), pack_bf16x2(cc2, d));
            asm volatile("st.shared.v2.b32 [%0], {%1, %2};"
                         :: "r"(ab + (uint32_t)(p * 2048)), "r"(packed.x), "r"(packed.y)
                         : "memory");
        }

        // issue next chunk's x loads (consumed after this chunk's MMAs)
        if (c < 3) {
            const float* nb = xbase + (c + 1) * 64;
            #pragma unroll
            for (int p = 0; p < 8; p++)
                v[p] = __ldcs(reinterpret_cast<const float4*>(nb + (size_t)p * 16 * DD));
        }

        // prefetch B for this warp's FIRST rotated q (latency hides under barrier)
        uint4 b4[4];
        {
            const int k16 = c * 4 + rot;
            #pragma unroll
            for (int jj = 0; jj < 4; jj++)
                b4[jj] = Bb[k16 * 256 + jj * 32];
        }

        __syncthreads();   // A[c&1] ready; MMA(c-1) finished on all warps

        const uint32_t lb = abase + (uint32_t)((c & 1) * 16384);
        #pragma unroll
        for (int q = 0; q < 4; q++) {
            const int qe = (q + rot) & 3;

            // prefetch next q's B before consuming current (depth-1 pipeline)
            uint4 bn[4];
            if (q < 3) {
                const int k16n = c * 4 + ((q + 1 + rot) & 3);
                #pragma unroll
                for (int jj = 0; jj < 4; jj++)
                    bn[jj] = Bb[k16n * 256 + jj * 32];
            }

            #pragma unroll
            for (int mt = 0; mt < 2; mt++) {
                const uint32_t addr = lb + (uint32_t)((row_l + mt * 16) * 128)
                                    + (((uint32_t)(qe * 32) + lds_koff) ^ lds_swz);
                uint32_t a0, a1, a2, a3;
                ldsm_x4(a0, a1, a2, a3, addr);
                #pragma unroll
                for (int jj = 0; jj < 4; jj++) {
                    mma16816(acc[mt][2 * jj],     a0, a1, a2, a3, b4[jj].x, b4[jj].y);
                    mma16816(acc[mt][2 * jj + 1], a0, a1, a2, a3, b4[jj].z, b4[jj].w);
                }
            }

            if (q < 3) {
                #pragma unroll
                for (int jj = 0; jj < 4; jj++) b4[jj] = bn[jj];
            }
        }
        // no trailing sync: next chunk's STS targets the other buffer;
        // the next __syncthreads orders MMA(c) before STS(c+2).
    }

    // ---- finalize x2 (reduce over the 16 lanes sharing a row) ----
    #pragma unroll
    for (int p = 0; p < 8; p++) {
        float w = x2p[p];
        w += __shfl_xor_sync(0xffffffffu, w, 1);
        w += __shfl_xor_sync(0xffffffffu, w, 2);
        w += __shfl_xor_sync(0xffffffffu, w, 4);
        w += __shfl_xor_sync(0xffffffffu, w, 8);
        if (scol == 0) x2_sh[p * 16 + srow] = w;
    }
    __syncthreads();   // x2 ready; all MMAs done -> smA reusable as fbuf

    // ---- epilogue: restage fragments -> coalesced streaming stores ----
    float* fb = reinterpret_cast<float*>(smA);   // 128 rows x 34 floats (17.4KB)
    const int rr = tid >> 3, f4 = tid & 7;

    #pragma unroll 1
    for (int cc = 0; cc < 4; cc++) {
        if (warp_n == (cc >> 1)) {
            #pragma unroll
            for (int ntl = 0; ntl < 4; ntl++) {
                const int nt = (cc & 1) * 4 + ntl;
                const int lcol = ntl * 8 + 2 * qlane;
                #pragma unroll
                for (int mt = 0; mt < 2; mt++) {
                    const int r0 = warp_m * 32 + mt * 16 + q8;
                    *reinterpret_cast<float2*>(fb + r0 * 34 + lcol) =
                        make_float2(acc[mt][nt][0], acc[mt][nt][1]);
                    *reinterpret_cast<float2*>(fb + (r0 + 8) * 34 + lcol) =
                        make_float2(acc[mt][nt][2], acc[mt][nt][3]);
                }
            }
        }
        __syncthreads();

        const int col0 = cc * 32 + f4 * 4;
        const float4 bp  = *reinterpret_cast<const float4*>(g_Bp + col0);
        const float4 svv = *reinterpret_cast<const float4*>(g_SV + col0);
        #pragma unroll
        for (int p = 0; p < 4; p++) {
            const int row = rr + p * 32;
            const float* ob = fb + row * 34 + f4 * 4;
            float2 u0 = *reinterpret_cast<const float2*>(ob);
            float2 u1 = *reinterpret_cast<const float2*>(ob + 2);
            const float x2v = x2_sh[row];
            float4 o;
            o.x = u0.x + bp.x - x2v * svv.x;
            o.y = u0.y + bp.y - x2v * svv.y;
            o.z = u1.x + bp.z - x2v * svv.z;
            o.w = u1.y + bp.w - x2v * svv.w;
            __stcs(reinterpret_cast<float4*>(out + (size_t)(row0 + row) * OUTD + col0), o);
        }
        __syncthreads();
    }
}

// ---------------- launcher ----------------
extern "C" void kernel_launch(void* const* d_in, const int* in_sizes, int n_in,
                              void* d_out, int out_size) {
    const float* x      = (const float*)d_in[0];  // [N, D]
    const float* center = (const float*)d_in[1];  // [K, D]
    const float* sigma  = (const float*)d_in[2];  // [D]
    const float* width  = (const float*)d_in[3];  // [K]
    const float* wout   = (const float*)d_in[4];  // [1+K, OUT]
    float* out = (float*)d_out;

    const int N = in_sizes[0] / DD;

    prep_kernel<<<OUTD / 2, 256>>>(sigma, center, width, wout);
    rbf_main_kernel<<<N / 128, 256>>>(x, out);
}

// round 8
// speedup vs baseline: 1.2360x; 1.2360x over previous
#include <cuda_runtime.h>
#include <cuda_bf16.h>
#include <cstdint>

// Problem constants (fixed shapes)
#define DD   256   // feature dim
#define KK   256   // num centers
#define OUTD 128   // output dim

// ---------------- constant precompute scratch (device globals) ----------------
__device__ __align__(16) float          g_s[DD];     // relu(sigma)
__device__ __align__(16) float          g_SV[OUTD];  // sum_k V[k,o]
__device__ __align__(16) float          g_Bp[OUTD];  // relu(W0)+sum relu(Wk) - sum c2*V
// Packed B fragments (bf16): uint4 index = (k16*8 + j)*32 + lane, j covers n-tiles {2j,2j+1}
__device__ __align__(16) __nv_bfloat16  g_Bpk[16 * 8 * 32 * 4 * 2];   // 64KB

// ---------------- packed-B writer ----------------
__device__ __forceinline__ void write_Bpk(int o, int d, float val) {
    int nt = o >> 3, q = o & 7;
    int k16 = d >> 4, r = d & 15;
    int i = r >> 3, l = (r & 7) >> 1, h = r & 1;
    int lane = q * 4 + l;
    int u32idx = ((k16 * 8 + (nt >> 1)) * 32 + lane) * 4 + (nt & 1) * 2 + i;
    g_Bpk[u32idx * 2 + h] = __float2bfloat16(val);
}

// ---------------- fused prep: SV, Bp, packed M2 — 2 output cols per block ------
__global__ void prep_kernel(const float* __restrict__ sigma,
                            const float* __restrict__ center,
                            const float* __restrict__ width,
                            const float* __restrict__ wout) {
    const int o0 = blockIdx.x * 2;
    const int o1 = o0 + 1;
    const int t = threadIdx.x;       // k index for reductions, d index for M2/CV
    __shared__ float V0[KK], V1[KK];
    __shared__ float red[6][8];

    const float s = fmaxf(sigma[t], 0.0f);
    if (blockIdx.x == 0) g_s[t] = s;

    float wk = fmaxf(width[t], 0.0f);
    float w0 = fmaxf(wout[(1 + t) * OUTD + o0], 0.0f);
    float w1 = fmaxf(wout[(1 + t) * OUTD + o1], 0.0f);
    float v0 = wk * w0, v1 = wk * w1;
    V0[t] = v0; V1[t] = v1;

    float r0 = v0, r1 = w0, r3 = v1, r4 = w1;
    #pragma unroll
    for (int off = 16; off; off >>= 1) {
        r0 += __shfl_xor_sync(0xffffffffu, r0, off);
        r1 += __shfl_xor_sync(0xffffffffu, r1, off);
        r3 += __shfl_xor_sync(0xffffffffu, r3, off);
        r4 += __shfl_xor_sync(0xffffffffu, r4, off);
    }
    const int warp = t >> 5, lane = t & 31;
    if (lane == 0) {
        red[0][warp] = r0; red[1][warp] = r1;
        red[3][warp] = r3; red[4][warp] = r4;
    }
    __syncthreads();   // V0/V1 ready

    // M2[d=t][o] = 2*sum_k c[k][t]*V[k][o];  CV partial: s_t * sum_k c[k][t]^2 * V[k][o]
    float m0 = 0, m1 = 0, q0 = 0, q1 = 0;
    #pragma unroll 4
    for (int k = 0; k < KK; k++) {
        float c = center[k * DD + t];
        float cs = c * c;
        m0 = fmaf(c, V0[k], m0);
        m1 = fmaf(c, V1[k], m1);
        q0 = fmaf(cs, V0[k], q0);
        q1 = fmaf(cs, V1[k], q1);
    }
    write_Bpk(o0, t, 2.0f * m0);
    write_Bpk(o1, t, 2.0f * m1);

    q0 *= s; q1 *= s;
    #pragma unroll
    for (int off = 16; off; off >>= 1) {
        q0 += __shfl_xor_sync(0xffffffffu, q0, off);
        q1 += __shfl_xor_sync(0xffffffffu, q1, off);
    }
    if (lane == 0) { red[2][warp] = q0; red[5][warp] = q1; }
    __syncthreads();

    if (t < 2) {
        const int o = (t == 0) ? o0 : o1;
        const float* a = red[3 * t];
        const float* b = red[3 * t + 1];
        const float* c = red[3 * t + 2];
        float sv = 0, sw = 0, cv = 0;
        #pragma unroll
        for (int w = 0; w < 8; w++) { sv += a[w]; sw += b[w]; cv += c[w]; }
        g_SV[o] = sv;
        g_Bp[o] = fmaxf(wout[o], 0.0f) + sw - cv;
    }
}

// ---------------- helpers ----------------
__device__ __forceinline__ uint32_t pack_bf16x2(float lo, float hi) {
    uint32_t r;
    asm("cvt.rn.bf16x2.f32 %0, %1, %2;" : "=r"(r) : "f"(hi), "f"(lo));
    return r;
}

__device__ __forceinline__ void mma16816(float* c, uint32_t a0, uint32_t a1,
                                         uint32_t a2, uint32_t a3,
                                         uint32_t b0, uint32_t b1) {
    asm volatile(
        "mma.sync.aligned.m16n8k16.row.col.f32.bf16.bf16.f32 "
        "{%0,%1,%2,%3}, {%4,%5,%6,%7}, {%8,%9}, {%0,%1,%2,%3};"
        : "+f"(c[0]), "+f"(c[1]), "+f"(c[2]), "+f"(c[3])
        : "r"(a0), "r"(a1), "r"(a2), "r"(a3), "r"(b0), "r"(b1));
}

__device__ __forceinline__ void ldsm_x4(uint32_t& r0, uint32_t& r1,
                                        uint32_t& r2, uint32_t& r3, uint32_t addr) {
    asm volatile("ldmatrix.sync.aligned.m8n8.x4.shared.b16 {%0,%1,%2,%3}, [%4];"
        : "=r"(r0), "=r"(r1), "=r"(r2), "=r"(r3) : "r"(addr));
}

// ---------------- main kernel: out = Bp - x2*SV + xs @ M2 ----------------
// 256 threads = 8 fully INDEPENDENT warps. Each warp: 16 rows x 128 cols,
// private double-buffered A tile, __syncwarp-only pipeline, private epilogue.
// NO __syncthreads anywhere: no phase-locking, no slowest-warp gating.
__global__ void __launch_bounds__(256, 2)
rbf_main_kernel(const float* __restrict__ x, float* __restrict__ out) {
    __shared__ __align__(16) char smA[8][4096];   // per-warp A (2 x 2KB double buffer)
    __shared__ float x2w[8][16];                  // per-warp x2 by local row

    const int tid  = threadIdx.x;
    const int warp = tid >> 5;
    const int lane = tid & 31;
    const int half = lane >> 4;      // 0/1: which row of the pair this lane loads
    const int seg  = lane & 15;      // 16B column segment
    const int q8   = lane >> 2;      // 0..7
    const int ql   = lane & 3;       // 0..3

    const int wrow0 = blockIdx.x * 128 + warp * 16;   // warp's first output row

    const uint32_t abase = (uint32_t)__cvta_generic_to_shared(&smA[warp][0]);
    const uint4* Bb = reinterpret_cast<const uint4*>(g_Bpk) + lane;

    // ldmatrix source address components (warp-local 16-row tile)
    const int rl = lane & 15;
    const uint32_t lds_swz  = (uint32_t)((rl & 7) << 4);
    const uint32_t lds_koff = (uint32_t)((lane >> 4) << 4);
    const uint32_t lds_row  = (uint32_t)(rl * 128);
    // STS address components: local row = 2p + half
    const uint32_t sts_col  = (uint32_t)(seg * 8);

    float acc[16][4];
    #pragma unroll
    for (int nt = 0; nt < 16; nt++)
        #pragma unroll
        for (int i = 0; i < 4; i++) acc[nt][i] = 0.0f;

    float x2p[8] = {0, 0, 0, 0, 0, 0, 0, 0};

    // prologue: chunk 0. LDG p covers rows {2p, 2p+1} (16 lanes each): 4 full lines.
    const float* xbase = x + (size_t)(wrow0 + half) * DD + seg * 4;
    float4 v[8];
    #pragma unroll
    for (int p = 0; p < 8; p++)
        v[p] = __ldcs(reinterpret_cast<const float4*>(xbase + (size_t)(2 * p) * DD));

    #pragma unroll
    for (int c = 0; c < 4; c++) {
        const float4 sv4 = *reinterpret_cast<const float4*>(g_s + c * 64 + seg * 4);
        const uint32_t ab = abase + (uint32_t)((c & 1) * 2048);

        // convert + x2 + STS into private buffer
        #pragma unroll
        for (int p = 0; p < 8; p++) {
            const float4 w = v[p];
            const int wrow = 2 * p + half;
            float a = w.x * sv4.x, b = w.y * sv4.y, cc2 = w.z * sv4.z, d = w.w * sv4.w;
            x2p[p] += a * w.x + b * w.y + cc2 * w.z + d * w.w;
            uint2 packed = make_uint2(pack_bf16x2(a, b), pack_bf16x2(cc2, d));
            const uint32_t off = (uint32_t)(wrow * 128) + (sts_col ^ (uint32_t)((wrow & 7) << 4));
            asm volatile("st.shared.v2.b32 [%0], {%1, %2};"
                         :: "r"(ab + off), "r"(packed.x), "r"(packed.y) : "memory");
        }

        // issue next chunk's x loads (hide DRAM latency under this chunk's MMAs)
        if (c < 3) {
            const float* nb = xbase + (c + 1) * 64;
            #pragma unroll
            for (int p = 0; p < 8; p++)
                v[p] = __ldcs(reinterpret_cast<const float4*>(nb + (size_t)(2 * p) * DD));
        }

        __syncwarp();   // STS visible to ldmatrix (warp-private, ~23 cyc)

        #pragma unroll
        for (int q = 0; q < 4; q++) {
            const int k16 = c * 4 + q;
            uint32_t a0, a1, a2, a3;
            ldsm_x4(a0, a1, a2, a3,
                    ab + lds_row + (((uint32_t)(q * 32) + lds_koff) ^ lds_swz));
            #pragma unroll
            for (int jj = 0; jj < 8; jj++) {
                const uint4 b4 = Bb[k16 * 256 + jj * 32];
                mma16816(acc[2 * jj],     a0, a1, a2, a3, b4.x, b4.y);
                mma16816(acc[2 * jj + 1], a0, a1, a2, a3, b4.z, b4.w);
            }
        }
        __syncwarp();   // LDSM(c) done before STS(c+2) reuses this buffer
    }

    // ---- finalize x2: reduce across the 16 lanes sharing each row ----
    #pragma unroll
    for (int p = 0; p < 8; p++) {
        float w = x2p[p];
        w += __shfl_xor_sync(0xffffffffu, w, 1);
        w += __shfl_xor_sync(0xffffffffu, w, 2);
        w += __shfl_xor_sync(0xffffffffu, w, 4);
        w += __shfl_xor_sync(0xffffffffu, w, 8);
        if (seg == 0) x2w[warp][2 * p + half] = w;
    }

    // ---- epilogue: warp-private restage -> coalesced STG.128 ----
    // fbuf: 16 rows x 36 floats (pad for 16B-aligned conflict-free LDS.128)
    float* fb = reinterpret_cast<float*>(&smA[warp][0]);
    const int erow = lane >> 3;          // 0..3
    const int ecol = lane & 7;           // 0..7 (float4 index)

    #pragma unroll 1
    for (int cc = 0; cc < 4; cc++) {
        __syncwarp();   // prior pass reads (or mainloop LDSM) complete
        #pragma unroll
        for (int ntl = 0; ntl < 4; ntl++) {
            const int nt = cc * 4 + ntl;
            const int lcol = ntl * 8 + 2 * ql;
            *reinterpret_cast<float2*>(fb + q8 * 36 + lcol) =
                make_float2(acc[nt][0], acc[nt][1]);
            *reinterpret_cast<float2*>(fb + (q8 + 8) * 36 + lcol) =
                make_float2(acc[nt][2], acc[nt][3]);
        }
        __syncwarp();

        const int col0 = cc * 32 + ecol * 4;
        const float4 bp  = *reinterpret_cast<const float4*>(g_Bp + col0);
        const float4 svv = *reinterpret_cast<const float4*>(g_SV + col0);
        #pragma unroll
        for (int i = 0; i < 4; i++) {
            const int row = erow + i * 4;
            const float4 u = *reinterpret_cast<const float4*>(fb + row * 36 + ecol * 4);
            const float x2v = x2w[warp][row];
            float4 o;
            o.x = u.x + bp.x - x2v * svv.x;
            o.y = u.y + bp.y - x2v * svv.y;
            o.z = u.z + bp.z - x2v * svv.z;
            o.w = u.w + bp.w - x2v * svv.w;
            __stcs(reinterpret_cast<float4*>(out + (size_t)(wrow0 + row) * OUTD + col0), o);
        }
    }
}

// ---------------- launcher ----------------
extern "C" void kernel_launch(void* const* d_in, const int* in_sizes, int n_in,
                              void* d_out, int out_size) {
    const float* x      = (const float*)d_in[0];  // [N, D]
    const float* center = (const float*)d_in[1];  // [K, D]
    const float* sigma  = (const float*)d_in[2];  // [D]
    const float* width  = (const float*)d_in[3];  // [K]
    const float* wout   = (const float*)d_in[4];  // [1+K, OUT]
    float* out = (float*)d_out;

    const int N = in_sizes[0] / DD;

    prep_kernel<<<OUTD / 2, 256>>>(sigma, center, width, wout);
    rbf_main_kernel<<<N / 128, 256>>>(x, out);
}

// round 9
// speedup vs baseline: 2.2716x; 1.8379x over previous
#include <cuda_runtime.h>
#include <cuda_bf16.h>
#include <cstdint>

// Problem constants (fixed shapes)
#define DD   256   // feature dim
#define KK   256   // num centers
#define OUTD 128   // output dim

// ---------------- constant precompute scratch (device globals) ----------------
__device__ __align__(16) float          g_s[DD];     // relu(sigma)
__device__ __align__(16) float          g_SV[OUTD];  // sum_k V[k,o]
__device__ __align__(16) float          g_Bp[OUTD];  // relu(W0)+sum relu(Wk) - sum c2*V
// Packed B' fragments (bf16), s pre-folded: uint4 idx = (k16*8 + j)*32 + lane
__device__ __align__(16) __nv_bfloat16  g_Bpk[16 * 8 * 32 * 4 * 2];   // 64KB

// ---------------- packed-B writer ----------------
__device__ __forceinline__ void write_Bpk(int o, int d, float val) {
    int nt = o >> 3, q = o & 7;
    int k16 = d >> 4, r = d & 15;
    int i = r >> 3, l = (r & 7) >> 1, h = r & 1;
    int lane = q * 4 + l;
    int u32idx = ((k16 * 8 + (nt >> 1)) * 32 + lane) * 4 + (nt & 1) * 2 + i;
    g_Bpk[u32idx * 2 + h] = __float2bfloat16(val);
}

// ---------------- fused prep: SV, Bp, packed s-folded M2 — 2 cols per block ----
__global__ void prep_kernel(const float* __restrict__ sigma,
                            const float* __restrict__ center,
                            const float* __restrict__ width,
                            const float* __restrict__ wout) {
    const int o0 = blockIdx.x * 2;
    const int o1 = o0 + 1;
    const int t = threadIdx.x;       // k index for reductions, d index for M2/CV
    __shared__ float V0[KK], V1[KK];
    __shared__ float red[6][8];

    const float s = fmaxf(sigma[t], 0.0f);
    if (blockIdx.x == 0) g_s[t] = s;

    float wk = fmaxf(width[t], 0.0f);
    float w0 = fmaxf(wout[(1 + t) * OUTD + o0], 0.0f);
    float w1 = fmaxf(wout[(1 + t) * OUTD + o1], 0.0f);
    float v0 = wk * w0, v1 = wk * w1;
    V0[t] = v0; V1[t] = v1;

    float r0 = v0, r1 = w0, r3 = v1, r4 = w1;
    #pragma unroll
    for (int off = 16; off; off >>= 1) {
        r0 += __shfl_xor_sync(0xffffffffu, r0, off);
        r1 += __shfl_xor_sync(0xffffffffu, r1, off);
        r3 += __shfl_xor_sync(0xffffffffu, r3, off);
        r4 += __shfl_xor_sync(0xffffffffu, r4, off);
    }
    const int warp = t >> 5, lane = t & 31;
    if (lane == 0) {
        red[0][warp] = r0; red[1][warp] = r1;
        red[3][warp] = r3; red[4][warp] = r4;
    }
    __syncthreads();   // V0/V1 ready

    // M2'[d=t][o] = s_t * 2 * sum_k c[k][t]*V[k][o]  (s folded into B)
    // CV partial:   s_t * sum_k c[k][t]^2 * V[k][o]
    float m0 = 0, m1 = 0, q0 = 0, q1 = 0;
    #pragma unroll 4
    for (int k = 0; k < KK; k++) {
        float c = center[k * DD + t];
        float cs = c * c;
        m0 = fmaf(c, V0[k], m0);
        m1 = fmaf(c, V1[k], m1);
        q0 = fmaf(cs, V0[k], q0);
        q1 = fmaf(cs, V1[k], q1);
    }
    write_Bpk(o0, t, 2.0f * s * m0);
    write_Bpk(o1, t, 2.0f * s * m1);

    q0 *= s; q1 *= s;
    #pragma unroll
    for (int off = 16; off; off >>= 1) {
        q0 += __shfl_xor_sync(0xffffffffu, q0, off);
        q1 += __shfl_xor_sync(0xffffffffu, q1, off);
    }
    if (lane == 0) { red[2][warp] = q0; red[5][warp] = q1; }
    __syncthreads();

    if (t < 2) {
        const int o = (t == 0) ? o0 : o1;
        const float* a = red[3 * t];
        const float* b = red[3 * t + 1];
        const float* c = red[3 * t + 2];
        float sv = 0, sw = 0, cv = 0;
        #pragma unroll
        for (int w = 0; w < 8; w++) { sv += a[w]; sw += b[w]; cv += c[w]; }
        g_SV[o] = sv;
        g_Bp[o] = fmaxf(wout[o], 0.0f) + sw - cv;
    }
}

// ---------------- helpers ----------------
__device__ __forceinline__ uint32_t pack_bf16x2(float lo, float hi) {
    uint32_t r;
    asm("cvt.rn.bf16x2.f32 %0, %1, %2;" : "=r"(r) : "f"(hi), "f"(lo));
    return r;
}

__device__ __forceinline__ void mma16816(float* c, uint32_t a0, uint32_t a1,
                                         uint32_t a2, uint32_t a3,
                                         uint32_t b0, uint32_t b1) {
    asm volatile(
        "mma.sync.aligned.m16n8k16.row.col.f32.bf16.bf16.f32 "
        "{%0,%1,%2,%3}, {%4,%5,%6,%7}, {%8,%9}, {%0,%1,%2,%3};"
        : "+f"(c[0]), "+f"(c[1]), "+f"(c[2]), "+f"(c[3])
        : "r"(a0), "r"(a1), "r"(a2), "r"(a3), "r"(b0), "r"(b1));
}

__device__ __forceinline__ void ldsm_x4(uint32_t& r0, uint32_t& r1,
                                        uint32_t& r2, uint32_t& r3, uint32_t addr) {
    asm volatile("ldmatrix.sync.aligned.m8n8.x4.shared.b16 {%0,%1,%2,%3}, [%4];"
        : "=r"(r0), "=r"(r1), "=r"(r2), "=r"(r3) : "r"(addr));
}

// ---------------- main kernel: out = Bp - x2*SV + x @ M2' ----------------
// 256 threads = 8 warps, warp grid 2(m) x 4(n), warp tile 32x32 (acc = 32 regs).
// Block tile 64 rows x 128 cols. Double-buffered A, ONE sync per chunk.
// __launch_bounds__(256,3): 24 warps/SM — occupancy is the lever this round.
__global__ void __launch_bounds__(256, 3)
rbf_main_kernel(const float* __restrict__ x, float* __restrict__ out) {
    __shared__ __align__(16) char smA[2][8192];   // 64 rows x 64 cols bf16, swizzled
    __shared__ float x2_sh[64];

    const int tid  = threadIdx.x;
    const int warp = tid >> 5;
    const int lane = tid & 31;
    const int warp_m = warp >> 2;     // 0..1
    const int warp_n = warp & 3;      // 0..3
    const int q8    = lane >> 2;      // 0..7
    const int ql    = lane & 3;       // 0..3

    const int row0 = blockIdx.x * 64;
    const int srow = tid >> 4;        // 0..15
    const int scol = tid & 15;        // 0..15

    const uint32_t abase = (uint32_t)__cvta_generic_to_shared(smA);
    const uint4* Bb = reinterpret_cast<const uint4*>(g_Bpk) + warp_n * 64 + lane;
    const int row_l = warp_m * 32 + (lane & 15);
    const uint32_t lds_swz  = (uint32_t)((row_l & 7) << 4);
    const uint32_t lds_koff = (uint32_t)((lane >> 4) << 4);
    const uint32_t sts_off  = (uint32_t)(srow * 128 + ((scol * 8) ^ ((srow & 7) << 4)));

    float acc[2][4][4];
    #pragma unroll
    for (int mt = 0; mt < 2; mt++)
        #pragma unroll
        for (int nt = 0; nt < 4; nt++)
            #pragma unroll
            for (int i = 0; i < 4; i++) acc[mt][nt][i] = 0.0f;

    float x2p[4] = {0, 0, 0, 0};

    // prologue: chunk 0 — rows p*16+srow, coalesced LDG.128
    const float* xbase = x + (size_t)(row0 + srow) * DD + scol * 4;
    float4 v[4];
    #pragma unroll
    for (int p = 0; p < 4; p++)
        v[p] = __ldcs(reinterpret_cast<const float4*>(xbase + (size_t)p * 16 * DD));

    #pragma unroll
    for (int c = 0; c < 4; c++) {
        const float4 sv4 = *reinterpret_cast<const float4*>(g_s + c * 64 + scol * 4);
        const uint32_t ab = abase + (uint32_t)((c & 1) * 8192);

        // x2 accumulate + pack RAW x (s folded into B') + STS
        #pragma unroll
        for (int p = 0; p < 4; p++) {
            const float4 w = v[p];
            float t0 = w.x * sv4.x, t1 = w.y * sv4.y;
            float t2 = w.z * sv4.z, t3 = w.w * sv4.w;
            x2p[p] += t0 * w.x + t1 * w.y + t2 * w.z + t3 * w.w;
            uint2 packed = make_uint2(pack_bf16x2(w.x, w.y), pack_bf16x2(w.z, w.w));
            asm volatile("st.shared.v2.b32 [%0], {%1, %2};"
                         :: "r"(ab + sts_off + (uint32_t)(p * 2048)),
                            "r"(packed.x), "r"(packed.y) : "memory");
        }

        // prefetch next chunk's x (consumed after this chunk's MMAs)
        if (c < 3) {
            const float* nb = xbase + (c + 1) * 64;
            #pragma unroll
            for (int p = 0; p < 4; p++)
                v[p] = __ldcs(reinterpret_cast<const float4*>(nb + (size_t)p * 16 * DD));
        }

        __syncthreads();   // A[c&1] ready; also orders MMA(c-1) before STS(c+1)

        const uint32_t lb = abase + (uint32_t)((c & 1) * 8192);
        #pragma unroll
        for (int q = 0; q < 4; q++) {
            const int k16 = c * 4 + q;
            const uint4 bu0 = Bb[k16 * 256];
            const uint4 bu1 = Bb[k16 * 256 + 32];

            #pragma unroll
            for (int mt = 0; mt < 2; mt++) {
                const uint32_t addr = lb + (uint32_t)((row_l + mt * 16) * 128)
                                    + (((uint32_t)(q * 32) + lds_koff) ^ lds_swz);
                uint32_t a0, a1, a2, a3;
                ldsm_x4(a0, a1, a2, a3, addr);
                mma16816(acc[mt][0], a0, a1, a2, a3, bu0.x, bu0.y);
                mma16816(acc[mt][1], a0, a1, a2, a3, bu0.z, bu0.w);
                mma16816(acc[mt][2], a0, a1, a2, a3, bu1.x, bu1.y);
                mma16816(acc[mt][3], a0, a1, a2, a3, bu1.z, bu1.w);
            }
        }
        // no trailing sync: double buffer + next chunk's sync provides ordering
    }

    // ---- finalize x2: reduce across the 16 lanes sharing each row ----
    #pragma unroll
    for (int p = 0; p < 4; p++) {
        float w = x2p[p];
        w += __shfl_xor_sync(0xffffffffu, w, 1);
        w += __shfl_xor_sync(0xffffffffu, w, 2);
        w += __shfl_xor_sync(0xffffffffu, w, 4);
        w += __shfl_xor_sync(0xffffffffu, w, 8);
        if (scol == 0) x2_sh[p * 16 + srow] = w;
    }
    __syncthreads();   // x2 ready; all MMAs done -> smA reusable as fbuf

    // ---- epilogue: restage fragments -> coalesced streaming stores ----
    float* fb = reinterpret_cast<float*>(smA);   // 64 rows x 36 floats (9.2KB)
    const int rr = tid >> 3, f4 = tid & 7;

    #pragma unroll 1
    for (int cc = 0; cc < 4; cc++) {
        if (warp_n == cc) {
            #pragma unroll
            for (int ntl = 0; ntl < 4; ntl++) {
                const int lcol = ntl * 8 + 2 * ql;
                #pragma unroll
                for (int mt = 0; mt < 2; mt++) {
                    const int r0 = warp_m * 32 + mt * 16 + q8;
                    *reinterpret_cast<float2*>(fb + r0 * 36 + lcol) =
                        make_float2(acc[mt][ntl][0], acc[mt][ntl][1]);
                    *reinterpret_cast<float2*>(fb + (r0 + 8) * 36 + lcol) =
                        make_float2(acc[mt][ntl][2], acc[mt][ntl][3]);
                }
            }
        }
        __syncthreads();

        const int col0 = cc * 32 + f4 * 4;
        const float4 bp  = *reinterpret_cast<const float4*>(g_Bp + col0);
        const float4 svv = *reinterpret_cast<const float4*>(g_SV + col0);
        #pragma unroll
        for (int i = 0; i < 2; i++) {
            const int row = rr + i * 32;
            const float4 u = *reinterpret_cast<const float4*>(fb + row * 36 + f4 * 4);
            const float x2v = x2_sh[row];
            float4 o;
            o.x = u.x + bp.x - x2v * svv.x;
            o.y = u.y + bp.y - x2v * svv.y;
            o.z = u.z + bp.z - x2v * svv.z;
            o.w = u.w + bp.w - x2v * svv.w;
            __stcs(reinterpret_cast<float4*>(out + (size_t)(row0 + row) * OUTD + col0), o);
        }
        __syncthreads();
    }
}

// ---------------- launcher ----------------
extern "C" void kernel_launch(void* const* d_in, const int* in_sizes, int n_in,
                              void* d_out, int out_size) {
    const float* x      = (const float*)d_in[0];  // [N, D]
    const float* center = (const float*)d_in[1];  // [K, D]
    const float* sigma  = (const float*)d_in[2];  // [D]
    const float* width  = (const float*)d_in[3];  // [K]
    const float* wout   = (const float*)d_in[4];  // [1+K, OUT]
    float* out = (float*)d_out;

    const int N = in_sizes[0] / DD;

    prep_kernel<<<OUTD / 2, 256>>>(sigma, center, width, wout);
    rbf_main_kernel<<<N / 64, 256>>>(x, out);
}

// round 10
// speedup vs baseline: 2.2939x; 1.0098x over previous
#include <cuda_runtime.h>
#include <cuda_bf16.h>
#include <cstdint>

// Problem constants (fixed shapes)
#define DD   256   // feature dim
#define KK   256   // num centers
#define OUTD 128   // output dim

// ---------------- constant precompute scratch (device globals) ----------------
__device__ __align__(16) float          g_s[DD];     // relu(sigma)
__device__ __align__(16) float          g_SV[OUTD];  // sum_k V[k,o]
__device__ __align__(16) float          g_Bp[OUTD];  // relu(W0)+sum relu(Wk) - sum c2*V
// Packed B' fragments (bf16), s pre-folded: uint4 idx = (k16*8 + j)*32 + lane
__device__ __align__(16) __nv_bfloat16  g_Bpk[16 * 8 * 32 * 4 * 2];   // 64KB

// ---------------- packed-B writer ----------------
__device__ __forceinline__ void write_Bpk(int o, int d, float val) {
    int nt = o >> 3, q = o & 7;
    int k16 = d >> 4, r = d & 15;
    int i = r >> 3, l = (r & 7) >> 1, h = r & 1;
    int lane = q * 4 + l;
    int u32idx = ((k16 * 8 + (nt >> 1)) * 32 + lane) * 4 + (nt & 1) * 2 + i;
    g_Bpk[u32idx * 2 + h] = __float2bfloat16(val);
}

// ---------------- fused prep: SV, Bp, packed s-folded M2 — 2 cols per block ----
__global__ void prep_kernel(const float* __restrict__ sigma,
                            const float* __restrict__ center,
                            const float* __restrict__ width,
                            const float* __restrict__ wout) {
    const int o0 = blockIdx.x * 2;
    const int o1 = o0 + 1;
    const int t = threadIdx.x;       // k index for reductions, d index for M2/CV
    __shared__ float V0[KK], V1[KK];
    __shared__ float red[6][8];

    const float s = fmaxf(sigma[t], 0.0f);
    if (blockIdx.x == 0) g_s[t] = s;

    float wk = fmaxf(width[t], 0.0f);
    float w0 = fmaxf(wout[(1 + t) * OUTD + o0], 0.0f);
    float w1 = fmaxf(wout[(1 + t) * OUTD + o1], 0.0f);
    float v0 = wk * w0, v1 = wk * w1;
    V0[t] = v0; V1[t] = v1;

    float r0 = v0, r1 = w0, r3 = v1, r4 = w1;
    #pragma unroll
    for (int off = 16; off; off >>= 1) {
        r0 += __shfl_xor_sync(0xffffffffu, r0, off);
        r1 += __shfl_xor_sync(0xffffffffu, r1, off);
        r3 += __shfl_xor_sync(0xffffffffu, r3, off);
        r4 += __shfl_xor_sync(0xffffffffu, r4, off);
    }
    const int warp = t >> 5, lane = t & 31;
    if (lane == 0) {
        red[0][warp] = r0; red[1][warp] = r1;
        red[3][warp] = r3; red[4][warp] = r4;
    }
    __syncthreads();   // V0/V1 ready

    // M2'[d=t][o] = s_t * 2 * sum_k c[k][t]*V[k][o]  (s folded into B)
    // CV partial:   s_t * sum_k c[k][t]^2 * V[k][o]
    // dual accumulators + unroll 8 -> MLP ~8 on the k-chain
    float m0a = 0, m0b = 0, m1a = 0, m1b = 0;
    float q0a = 0, q0b = 0, q1a = 0, q1b = 0;
    #pragma unroll 8
    for (int k = 0; k < KK; k += 2) {
        float ca = center[k * DD + t];
        float cb = center[(k + 1) * DD + t];
        float csa = ca * ca, csb = cb * cb;
        m0a = fmaf(ca, V0[k], m0a);      m0b = fmaf(cb, V0[k + 1], m0b);
        m1a = fmaf(ca, V1[k], m1a);      m1b = fmaf(cb, V1[k + 1], m1b);
        q0a = fmaf(csa, V0[k], q0a);     q0b = fmaf(csb, V0[k + 1], q0b);
        q1a = fmaf(csa, V1[k], q1a);     q1b = fmaf(csb, V1[k + 1], q1b);
    }
    write_Bpk(o0, t, 2.0f * s * (m0a + m0b));
    write_Bpk(o1, t, 2.0f * s * (m1a + m1b));

    float q0 = s * (q0a + q0b), q1 = s * (q1a + q1b);
    #pragma unroll
    for (int off = 16; off; off >>= 1) {
        q0 += __shfl_xor_sync(0xffffffffu, q0, off);
        q1 += __shfl_xor_sync(0xffffffffu, q1, off);
    }
    if (lane == 0) { red[2][warp] = q0; red[5][warp] = q1; }
    __syncthreads();

    if (t < 2) {
        const int o = (t == 0) ? o0 : o1;
        const float* a = red[3 * t];
        const float* b = red[3 * t + 1];
        const float* c = red[3 * t + 2];
        float sv = 0, sw = 0, cv = 0;
        #pragma unroll
        for (int w = 0; w < 8; w++) { sv += a[w]; sw += b[w]; cv += c[w]; }
        g_SV[o] = sv;
        g_Bp[o] = fmaxf(wout[o], 0.0f) + sw - cv;
    }
}

// ---------------- helpers ----------------
__device__ __forceinline__ uint32_t pack_bf16x2(float lo, float hi) {
    uint32_t r;
    asm("cvt.rn.bf16x2.f32 %0, %1, %2;" : "=r"(r) : "f"(hi), "f"(lo));
    return r;
}

__device__ __forceinline__ void mma16816(float* c, uint32_t a0, uint32_t a1,
                                         uint32_t a2, uint32_t a3,
                                         uint32_t b0, uint32_t b1) {
    asm volatile(
        "mma.sync.aligned.m16n8k16.row.col.f32.bf16.bf16.f32 "
        "{%0,%1,%2,%3}, {%4,%5,%6,%7}, {%8,%9}, {%0,%1,%2,%3};"
        : "+f"(c[0]), "+f"(c[1]), "+f"(c[2]), "+f"(c[3])
        : "r"(a0), "r"(a1), "r"(a2), "r"(a3), "r"(b0), "r"(b1));
}

__device__ __forceinline__ void ldsm_x4(uint32_t& r0, uint32_t& r1,
                                        uint32_t& r2, uint32_t& r3, uint32_t addr) {
    asm volatile("ldmatrix.sync.aligned.m8n8.x4.shared.b16 {%0,%1,%2,%3}, [%4];"
        : "=r"(r0), "=r"(r1), "=r"(r2), "=r"(r3) : "r"(addr));
}

// ---------------- main kernel: out = Bp - x2*SV + x @ M2' ----------------
// 256 threads = 8 warps, 2(m) x 4(n), warp tile 32x32 (acc = 32 regs).
// Block tile 64 rows x 128 cols. 8 chunks of 32 k-cols, v[2] staging.
// A tile: 64 rows x 128B; the two chunk buffers live in the two 64B halves
// of each swizzled row (XOR-disjoint). __launch_bounds__(256,4): 32 warps/SM.
__global__ void __launch_bounds__(256, 4)
rbf_main_kernel(const float* __restrict__ x, float* __restrict__ out) {
    __shared__ __align__(16) char smU[64 * 68 * 4];   // union: A (8KB) / fbuf (17KB)
    __shared__ float x2_sh[64];

    const int tid  = threadIdx.x;
    const int warp = tid >> 5;
    const int lane = tid & 31;
    const int warp_m = warp >> 2;     // 0..1
    const int warp_n = warp & 3;      // 0..3
    const int q8    = lane >> 2;      // 0..7
    const int ql    = lane & 3;       // 0..3

    const int row0 = blockIdx.x * 64;
    const int base2 = tid >> 3;       // 0..31: staging row group (rows 2*base2 + p)
    const int seg   = tid & 7;        // 16B segment within 32-col chunk

    const uint32_t abase = (uint32_t)__cvta_generic_to_shared(smU);
    const uint4* Bb = reinterpret_cast<const uint4*>(g_Bpk) + warp_n * 64 + lane;

    // STS components (rows 2*base2 + p)
    const int sr0 = base2 * 2;
    const uint32_t sts_b0 = abase + (uint32_t)(sr0 * 128);
    const uint32_t sts_w0 = (uint32_t)((sr0 & 7) << 4);
    const uint32_t sts_w1 = (uint32_t)(((sr0 + 1) & 7) << 4);
    const uint32_t su = (uint32_t)(seg * 8);

    // ldmatrix components
    const int rl0 = warp_m * 32 + (lane & 15);
    const uint32_t lds_b0 = abase + (uint32_t)(rl0 * 128);
    const uint32_t lds_w0 = (uint32_t)((rl0 & 7) << 4);
    const uint32_t koff = (uint32_t)((lane >> 4) << 4);

    float acc[2][4][4];
    #pragma unroll
    for (int mt = 0; mt < 2; mt++)
        #pragma unroll
        for (int nt = 0; nt < 4; nt++)
            #pragma unroll
            for (int i = 0; i < 4; i++) acc[mt][nt][i] = 0.0f;

    float x2p0 = 0.0f, x2p1 = 0.0f;

    const float* xptr = x + (size_t)(row0 + sr0) * DD + seg * 4;
    float4 v0 = __ldcs(reinterpret_cast<const float4*>(xptr));
    float4 v1 = __ldcs(reinterpret_cast<const float4*>(xptr + DD));

    #pragma unroll
    for (int c = 0; c < 8; c++) {
        const float4 sv4 = *reinterpret_cast<const float4*>(g_s + c * 32 + seg * 4);
        const uint32_t half64 = (uint32_t)((c & 1) << 6);

        // x2 + pack raw x + STS (2 rows)
        {
            float t0 = v0.x * sv4.x, t1 = v0.y * sv4.y, t2 = v0.z * sv4.z, t3 = v0.w * sv4.w;
            x2p0 += t0 * v0.x + t1 * v0.y + t2 * v0.z + t3 * v0.w;
            uint2 pk = make_uint2(pack_bf16x2(v0.x, v0.y), pack_bf16x2(v0.z, v0.w));
            asm volatile("st.shared.v2.b32 [%0], {%1, %2};"
                :: "r"(sts_b0 + (((half64 | su) ^ sts_w0))), "r"(pk.x), "r"(pk.y) : "memory");
        }
        {
            float t0 = v1.x * sv4.x, t1 = v1.y * sv4.y, t2 = v1.z * sv4.z, t3 = v1.w * sv4.w;
            x2p1 += t0 * v1.x + t1 * v1.y + t2 * v1.z + t3 * v1.w;
            uint2 pk = make_uint2(pack_bf16x2(v1.x, v1.y), pack_bf16x2(v1.z, v1.w));
            asm volatile("st.shared.v2.b32 [%0], {%1, %2};"
                :: "r"(sts_b0 + 128u + (((half64 | su) ^ sts_w1))), "r"(pk.x), "r"(pk.y) : "memory");
        }

        // prefetch next chunk's x
        if (c < 7) {
            const float* nb = xptr + (c + 1) * 32;
            v0 = __ldcs(reinterpret_cast<const float4*>(nb));
            v1 = __ldcs(reinterpret_cast<const float4*>(nb + DD));
        }

        __syncthreads();   // A half ready; also orders MMA(c-1) before STS(c+1)

        #pragma unroll
        for (int q = 0; q < 2; q++) {
            const int k16 = c * 2 + q;
            const uint4 bu0 = Bb[k16 * 256];
            const uint4 bu1 = Bb[k16 * 256 + 32];
            const uint32_t u = half64 + (uint32_t)(q * 32) + koff;

            #pragma unroll
            for (int mt = 0; mt < 2; mt++) {
                const uint32_t addr = lds_b0 + (uint32_t)(mt * 16 * 128)
                                    + (u ^ lds_w0);
                uint32_t a0, a1, a2, a3;
                ldsm_x4(a0, a1, a2, a3, addr);
                mma16816(acc[mt][0], a0, a1, a2, a3, bu0.x, bu0.y);
                mma16816(acc[mt][1], a0, a1, a2, a3, bu0.z, bu0.w);
                mma16816(acc[mt][2], a0, a1, a2, a3, bu1.x, bu1.y);
                mma16816(acc[mt][3], a0, a1, a2, a3, bu1.z, bu1.w);
            }
        }
        // no trailing sync: halves alternate; next sync provides ordering
    }

    // ---- finalize x2: reduce across the 8 lanes sharing each row ----
    x2p0 += __shfl_xor_sync(0xffffffffu, x2p0, 1);
    x2p0 += __shfl_xor_sync(0xffffffffu, x2p0, 2);
    x2p0 += __shfl_xor_sync(0xffffffffu, x2p0, 4);
    x2p1 += __shfl_xor_sync(0xffffffffu, x2p1, 1);
    x2p1 += __shfl_xor_sync(0xffffffffu, x2p1, 2);
    x2p1 += __shfl_xor_sync(0xffffffffu, x2p1, 4);
    if (seg == 0) {
        x2_sh[sr0] = x2p0;
        x2_sh[sr0 + 1] = x2p1;
    }
    __syncthreads();   // x2 ready; all MMAs done -> smU reusable as fbuf

    // ---- epilogue: 2 passes x 64 cols; restage -> coalesced STG.128 ----
    float* fb = reinterpret_cast<float*>(smU);   // 64 rows x 68 floats
    const int rr2 = tid >> 4;      // 0..15
    const int f4  = tid & 15;      // 0..15 float4 col within 64

    #pragma unroll 1
    for (int cc = 0; cc < 2; cc++) {
        if ((warp_n >> 1) == cc) {
            #pragma unroll
            for (int ntl = 0; ntl < 4; ntl++) {
                const int lcol = (warp_n & 1) * 32 + ntl * 8 + 2 * ql;
                #pragma unroll
                for (int mt = 0; mt < 2; mt++) {
                    const int r0 = warp_m * 32 + mt * 16 + q8;
                    *reinterpret_cast<float2*>(fb + r0 * 68 + lcol) =
                        make_float2(acc[mt][ntl][0], acc[mt][ntl][1]);
                    *reinterpret_cast<float2*>(fb + (r0 + 8) * 68 + lcol) =
                        make_float2(acc[mt][ntl][2], acc[mt][ntl][3]);
                }
            }
        }
        __syncthreads();

        const int col0 = cc * 64 + f4 * 4;
        const float4 bp  = *reinterpret_cast<const float4*>(g_Bp + col0);
        const float4 svv = *reinterpret_cast<const float4*>(g_SV + col0);
        #pragma unroll
        for (int i = 0; i < 4; i++) {
            const int row = rr2 + i * 16;
            const float4 u = *reinterpret_cast<const float4*>(fb + row * 68 + f4 * 4);
            const float x2v = x2_sh[row];
            float4 o;
            o.x = u.x + bp.x - x2v * svv.x;
            o.y = u.y + bp.y - x2v * svv.y;
            o.z = u.z + bp.z - x2v * svv.z;
            o.w = u.w + bp.w - x2v * svv.w;
            __stcs(reinterpret_cast<float4*>(out + (size_t)(row0 + row) * OUTD + col0), o);
        }
        __syncthreads();
    }
}

// ---------------- launcher ----------------
extern "C" void kernel_launch(void* const* d_in, const int* in_sizes, int n_in,
                              void* d_out, int out_size) {
    const float* x      = (const float*)d_in[0];  // [N, D]
    const float* center = (const float*)d_in[1];  // [K, D]
    const float* sigma  = (const float*)d_in[2];  // [D]
    const float* width  = (const float*)d_in[3];  // [K]
    const float* wout   = (const float*)d_in[4];  // [1+K, OUT]
    float* out = (float*)d_out;

    const int N = in_sizes[0] / DD;

    prep_kernel<<<OUTD / 2, 256>>>(sigma, center, width, wout);
    rbf_main_kernel<<<N / 64, 256>>>(x, out);
}